// round 14
// baseline (speedup 1.0000x reference)
#include <cuda_runtime.h>
#include <math.h>

// out[n,j] = (x[n]==0 ? 0 : W[x[n],j]) + pe(n+1, j)
// pe(pos,j): even j -> cos(pos*w_{j/2}); odd j -> sin(pos*w_{(j+1)/2}); w_m = 1e-4^(m/512)
//
// R13: QUARTER column passes + WRITE-THROUGH stores.
// R12's profiled pass proved the L2-residency scheme works in isolation (381MB
// = compulsory-only), but steady state degraded -> hypothesis: the 256MB/pass
// store stream allocates in L2 and evicts the 103MB half-table. Fixes:
//   - __stwt output stores (no L2 allocation for the write stream)
//   - 4 passes of 256 cols: per-pass table = 51.5MB << 126MB L2
// pe numerics identical to R11/R12 (lane-0 cosf fallback at every warp boundary;
// libdevice cosf == sincosf's cos) -> rel_err must stay 2.179366e-4.

#define DHID 1024
#define QCOLS 64           // float4 col-groups per pass (256 columns)
#define TPB 64
#define ROWS_PER_CTA 32
#define UNROLL 4
#define ANGLE_T 25000.0f

__device__ __forceinline__ float4 ldg_hint(const float4* p, unsigned long long pol) {
    float4 v;
    asm volatile("ld.global.nc.L2::cache_hint.v4.f32 {%0,%1,%2,%3}, [%4], %5;"
                 : "=f"(v.x), "=f"(v.y), "=f"(v.z), "=f"(v.w) : "l"(p), "l"(pol));
    return v;
}

__global__ __launch_bounds__(TPB)
void pe_embed_q_kernel(const int* __restrict__ x,
                       const float4* __restrict__ W4,
                       float4* __restrict__ out4,
                       int N, int colq0)
{
    const int tl   = threadIdx.x;          // 0..63 within the quarter
    const int t    = colq0 + tl;           // global float4 index (0..255)
    const int lane = tl & 31;
    const long long row0 = (long long)blockIdx.x * ROWS_PER_CTA;
    if (row0 >= N) return;
    const long long rend = (row0 + ROWS_PER_CTA < (long long)N) ? row0 + ROWS_PER_CTA
                                                                : (long long)N;

    const float base   = 1.0f / 10000.0f;
    const float inv512 = 1.0f / 512.0f;
    const float w0 = powf(base, (float)(2 * t    ) * inv512);
    const float w1 = powf(base, (float)(2 * t + 1) * inv512);
    const float w2 = powf(base, (float)(2 * t + 2) * inv512);

    const float wmax  = __shfl_sync(0xFFFFFFFFu, w0, 0);
    const bool  exact = ((float)rend * wmax) > ANGLE_T;
    const bool  full  = ((rend - row0) % UNROLL) == 0;

    unsigned long long pol;
    asm("createpolicy.fractional.L2::evict_last.b64 %0, 1.0;" : "=l"(pol));

    if (exact) {
        if (full) {
            int idx[UNROLL];
            #pragma unroll
            for (int k = 0; k < UNROLL; ++k) idx[k] = __ldg(&x[row0 + k]);

            for (long long n = row0; n < rend; n += UNROLL) {
                float4 e[UNROLL];
                #pragma unroll
                for (int k = 0; k < UNROLL; ++k) {
                    e[k] = make_float4(0.f, 0.f, 0.f, 0.f);
                    if (idx[k] != 0)
                        e[k] = ldg_hint(&W4[(long long)idx[k] * (DHID / 4) + t], pol);
                }
                if (n + UNROLL < rend) {
                    #pragma unroll
                    for (int k = 0; k < UNROLL; ++k) idx[k] = __ldg(&x[n + UNROLL + k]);
                }
                #pragma unroll
                for (int k = 0; k < UNROLL; ++k) {
                    const float pos = (float)(n + k + 1);
                    float sA, cA, sB, cB;
                    sincosf(pos * w1, &sA, &cA);
                    sincosf(pos * w2, &sB, &cB);
                    float c0 = __shfl_up_sync(0xFFFFFFFFu, cB, 1);
                    if (lane == 0) c0 = cosf(pos * w0);
                    float4 o;
                    o.x = e[k].x + c0;
                    o.y = e[k].y + sA;
                    o.z = e[k].z + cA;
                    o.w = e[k].w + sB;
                    __stwt(&out4[(n + k) * (DHID / 4) + t], o);
                }
            }
        } else {
            for (long long n = row0; n < rend; ++n) {
                const float pos = (float)(n + 1);
                float sA, cA, sB, cB;
                sincosf(pos * w1, &sA, &cA);
                sincosf(pos * w2, &sB, &cB);
                float c0 = __shfl_up_sync(0xFFFFFFFFu, cB, 1);
                if (lane == 0) c0 = cosf(pos * w0);
                const int idx = __ldg(&x[n]);
                float4 e = make_float4(0.f, 0.f, 0.f, 0.f);
                if (idx != 0) e = ldg_hint(&W4[(long long)idx * (DHID / 4) + t], pol);
                float4 o;
                o.x = e.x + c0; o.y = e.y + sA; o.z = e.z + cA; o.w = e.w + sB;
                __stwt(&out4[n * (DHID / 4) + t], o);
            }
        }
    } else {
        const float pos0 = (float)(row0 + 1);
        float s0, c0, s1, c1, s2, c2;
        sincosf(pos0 * w0, &s0, &c0);
        sincosf(pos0 * w1, &s1, &c1);
        sincosf(pos0 * w2, &s2, &c2);
        float sw0, cw0, sw1, cw1, sw2, cw2;
        sincosf(w0, &sw0, &cw0);
        sincosf(w1, &sw1, &cw1);
        sincosf(w2, &sw2, &cw2);

        if (full) {
            int idx[UNROLL];
            #pragma unroll
            for (int k = 0; k < UNROLL; ++k) idx[k] = __ldg(&x[row0 + k]);

            for (long long n = row0; n < rend; n += UNROLL) {
                float4 e[UNROLL];
                #pragma unroll
                for (int k = 0; k < UNROLL; ++k) {
                    e[k] = make_float4(0.f, 0.f, 0.f, 0.f);
                    if (idx[k] != 0)
                        e[k] = ldg_hint(&W4[(long long)idx[k] * (DHID / 4) + t], pol);
                }
                if (n + UNROLL < rend) {
                    #pragma unroll
                    for (int k = 0; k < UNROLL; ++k) idx[k] = __ldg(&x[n + UNROLL + k]);
                }
                #pragma unroll
                for (int k = 0; k < UNROLL; ++k) {
                    float4 o;
                    o.x = e[k].x + c0;
                    o.y = e[k].y + s1;
                    o.z = e[k].z + c1;
                    o.w = e[k].w + s2;
                    __stwt(&out4[(n + k) * (DHID / 4) + t], o);

                    float ns0 = fmaf(s0, cw0,  c0 * sw0);
                    float nc0 = fmaf(c0, cw0, -s0 * sw0);
                    float ns1 = fmaf(s1, cw1,  c1 * sw1);
                    float nc1 = fmaf(c1, cw1, -s1 * sw1);
                    float ns2 = fmaf(s2, cw2,  c2 * sw2);
                    float nc2 = fmaf(c2, cw2, -s2 * sw2);
                    s0 = ns0; c0 = nc0;
                    s1 = ns1; c1 = nc1;
                    s2 = ns2; c2 = nc2;
                }
            }
        } else {
            for (long long n = row0; n < rend; ++n) {
                const int idx = __ldg(&x[n]);
                float4 e = make_float4(0.f, 0.f, 0.f, 0.f);
                if (idx != 0) e = ldg_hint(&W4[(long long)idx * (DHID / 4) + t], pol);
                float4 o;
                o.x = e.x + c0; o.y = e.y + s1; o.z = e.z + c1; o.w = e.w + s2;
                __stwt(&out4[n * (DHID / 4) + t], o);

                float ns0 = fmaf(s0, cw0,  c0 * sw0);
                float nc0 = fmaf(c0, cw0, -s0 * sw0);
                float ns1 = fmaf(s1, cw1,  c1 * sw1);
                float nc1 = fmaf(c1, cw1, -s1 * sw1);
                float ns2 = fmaf(s2, cw2,  c2 * sw2);
                float nc2 = fmaf(c2, cw2, -s2 * sw2);
                s0 = ns0; c0 = nc0;
                s1 = ns1; c1 = nc1;
                s2 = ns2; c2 = nc2;
            }
        }
    }
}

extern "C" void kernel_launch(void* const* d_in, const int* in_sizes, int n_in,
                              void* d_out, int out_size)
{
    const int*   x   = (const int*)d_in[0];    // int32 [N]
    const float* W   = (const float*)d_in[1];  // f32 [V,1024]
    float*       out = (float*)d_out;          // f32 [N,1024]
    const int N = in_sizes[0];

    const int grid = (N + ROWS_PER_CTA - 1) / ROWS_PER_CTA;
    // Four sequential passes; each pass's 51.5MB quarter of W is L2-resident.
    pe_embed_q_kernel<<<grid, TPB>>>(x, (const float4*)W, (float4*)out, N, 0);
    pe_embed_q_kernel<<<grid, TPB>>>(x, (const float4*)W, (float4*)out, N, 64);
    pe_embed_q_kernel<<<grid, TPB>>>(x, (const float4*)W, (float4*)out, N, 128);
    pe_embed_q_kernel<<<grid, TPB>>>(x, (const float4*)W, (float4*)out, N, 192);
}

// round 15
// speedup vs baseline: 1.2454x; 1.2454x over previous
#include <cuda_runtime.h>
#include <math.h>

// out[n,j] = (x[n]==0 ? 0 : W[x[n],j]) + pe(n+1, j)
// pe(pos,j): even j -> cos(pos*w_{j/2}); odd j -> sin(pos*w_{(j+1)/2}); w_m = 1e-4^(m/512)
//
// R14 = R12 (190.7us: 2 column passes of 512 cols, each half-table 103MB L2-resident,
// __stcs evict-first stores) with ONE change: W gathers use plain __ldg instead of the
// evict_last cache hint. Mechanism: protected (evict_last) lines from pass p's table
// linger across the pass boundary and thrash pass p+1's table in steady state —
// ncu's cache flush hid this (isolated pass ran 66us vs ~95us timed). Plain LRU +
// evict-first stores keeps the active table resident without cross-pass poisoning.
// R13's __stwt (write-through) broke L2 write-combining -> reverted.
// Numerics identical to R11/R12 -> rel_err must stay 2.179366e-4.

#define DHID 1024
#define TPB 128            // one float4 per thread across the 512-col half
#define ROWS_PER_CTA 32
#define UNROLL 4
#define ANGLE_T 25000.0f

__global__ __launch_bounds__(TPB)
void pe_embed_half_kernel(const int* __restrict__ x,
                          const float4* __restrict__ W4,
                          float4* __restrict__ out4,
                          int N, int colq0)
{
    const int tl   = threadIdx.x;          // 0..127 within the half
    const int t    = colq0 + tl;           // global float4 index (0..255)
    const int lane = tl & 31;
    const long long row0 = (long long)blockIdx.x * ROWS_PER_CTA;
    if (row0 >= N) return;
    const long long rend = (row0 + ROWS_PER_CTA < (long long)N) ? row0 + ROWS_PER_CTA
                                                                : (long long)N;

    const float base   = 1.0f / 10000.0f;
    const float inv512 = 1.0f / 512.0f;
    const float w0 = powf(base, (float)(2 * t    ) * inv512);
    const float w1 = powf(base, (float)(2 * t + 1) * inv512);
    const float w2 = powf(base, (float)(2 * t + 2) * inv512);

    const float wmax  = __shfl_sync(0xFFFFFFFFu, w0, 0);
    const bool  exact = ((float)rend * wmax) > ANGLE_T;
    const bool  full  = ((rend - row0) % UNROLL) == 0;

    if (exact) {
        if (full) {
            int idx[UNROLL];
            #pragma unroll
            for (int k = 0; k < UNROLL; ++k) idx[k] = __ldg(&x[row0 + k]);

            for (long long n = row0; n < rend; n += UNROLL) {
                float4 e[UNROLL];
                #pragma unroll
                for (int k = 0; k < UNROLL; ++k) {
                    e[k] = make_float4(0.f, 0.f, 0.f, 0.f);
                    if (idx[k] != 0)
                        e[k] = __ldg(&W4[(long long)idx[k] * (DHID / 4) + t]);
                }
                if (n + UNROLL < rend) {
                    #pragma unroll
                    for (int k = 0; k < UNROLL; ++k) idx[k] = __ldg(&x[n + UNROLL + k]);
                }
                #pragma unroll
                for (int k = 0; k < UNROLL; ++k) {
                    const float pos = (float)(n + k + 1);
                    float sA, cA, sB, cB;
                    sincosf(pos * w1, &sA, &cA);
                    sincosf(pos * w2, &sB, &cB);
                    float c0 = __shfl_up_sync(0xFFFFFFFFu, cB, 1);
                    if (lane == 0) c0 = cosf(pos * w0);
                    float4 o;
                    o.x = e[k].x + c0;
                    o.y = e[k].y + sA;
                    o.z = e[k].z + cA;
                    o.w = e[k].w + sB;
                    __stcs(&out4[(n + k) * (DHID / 4) + t], o);
                }
            }
        } else {
            for (long long n = row0; n < rend; ++n) {
                const float pos = (float)(n + 1);
                float sA, cA, sB, cB;
                sincosf(pos * w1, &sA, &cA);
                sincosf(pos * w2, &sB, &cB);
                float c0 = __shfl_up_sync(0xFFFFFFFFu, cB, 1);
                if (lane == 0) c0 = cosf(pos * w0);
                const int idx = __ldg(&x[n]);
                float4 e = make_float4(0.f, 0.f, 0.f, 0.f);
                if (idx != 0) e = __ldg(&W4[(long long)idx * (DHID / 4) + t]);
                float4 o;
                o.x = e.x + c0; o.y = e.y + sA; o.z = e.z + cA; o.w = e.w + sB;
                __stcs(&out4[n * (DHID / 4) + t], o);
            }
        }
    } else {
        const float pos0 = (float)(row0 + 1);
        float s0, c0, s1, c1, s2, c2;
        sincosf(pos0 * w0, &s0, &c0);
        sincosf(pos0 * w1, &s1, &c1);
        sincosf(pos0 * w2, &s2, &c2);
        float sw0, cw0, sw1, cw1, sw2, cw2;
        sincosf(w0, &sw0, &cw0);
        sincosf(w1, &sw1, &cw1);
        sincosf(w2, &sw2, &cw2);

        if (full) {
            int idx[UNROLL];
            #pragma unroll
            for (int k = 0; k < UNROLL; ++k) idx[k] = __ldg(&x[row0 + k]);

            for (long long n = row0; n < rend; n += UNROLL) {
                float4 e[UNROLL];
                #pragma unroll
                for (int k = 0; k < UNROLL; ++k) {
                    e[k] = make_float4(0.f, 0.f, 0.f, 0.f);
                    if (idx[k] != 0)
                        e[k] = __ldg(&W4[(long long)idx[k] * (DHID / 4) + t]);
                }
                if (n + UNROLL < rend) {
                    #pragma unroll
                    for (int k = 0; k < UNROLL; ++k) idx[k] = __ldg(&x[n + UNROLL + k]);
                }
                #pragma unroll
                for (int k = 0; k < UNROLL; ++k) {
                    float4 o;
                    o.x = e[k].x + c0;
                    o.y = e[k].y + s1;
                    o.z = e[k].z + c1;
                    o.w = e[k].w + s2;
                    __stcs(&out4[(n + k) * (DHID / 4) + t], o);

                    float ns0 = fmaf(s0, cw0,  c0 * sw0);
                    float nc0 = fmaf(c0, cw0, -s0 * sw0);
                    float ns1 = fmaf(s1, cw1,  c1 * sw1);
                    float nc1 = fmaf(c1, cw1, -s1 * sw1);
                    float ns2 = fmaf(s2, cw2,  c2 * sw2);
                    float nc2 = fmaf(c2, cw2, -s2 * sw2);
                    s0 = ns0; c0 = nc0;
                    s1 = ns1; c1 = nc1;
                    s2 = ns2; c2 = nc2;
                }
            }
        } else {
            for (long long n = row0; n < rend; ++n) {
                const int idx = __ldg(&x[n]);
                float4 e = make_float4(0.f, 0.f, 0.f, 0.f);
                if (idx != 0) e = __ldg(&W4[(long long)idx * (DHID / 4) + t]);
                float4 o;
                o.x = e.x + c0; o.y = e.y + s1; o.z = e.z + c1; o.w = e.w + s2;
                __stcs(&out4[n * (DHID / 4) + t], o);

                float ns0 = fmaf(s0, cw0,  c0 * sw0);
                float nc0 = fmaf(c0, cw0, -s0 * sw0);
                float ns1 = fmaf(s1, cw1,  c1 * sw1);
                float nc1 = fmaf(c1, cw1, -s1 * sw1);
                float ns2 = fmaf(s2, cw2,  c2 * sw2);
                float nc2 = fmaf(c2, cw2, -s2 * sw2);
                s0 = ns0; c0 = nc0;
                s1 = ns1; c1 = nc1;
                s2 = ns2; c2 = nc2;
            }
        }
    }
}

extern "C" void kernel_launch(void* const* d_in, const int* in_sizes, int n_in,
                              void* d_out, int out_size)
{
    const int*   x   = (const int*)d_in[0];    // int32 [N]
    const float* W   = (const float*)d_in[1];  // f32 [V,1024]
    float*       out = (float*)d_out;          // f32 [N,1024]
    const int N = in_sizes[0];

    const int grid = (N + ROWS_PER_CTA - 1) / ROWS_PER_CTA;
    // Two sequential passes; each pass's 103MB half of W is L2-resident.
    pe_embed_half_kernel<<<grid, TPB>>>(x, (const float4*)W, (float4*)out, N, 0);
    pe_embed_half_kernel<<<grid, TPB>>>(x, (const float4*)W, (float4*)out, N, 128);
}